// round 6
// baseline (speedup 1.0000x reference)
#include <cuda_runtime.h>
#include <cstdint>

#define NWORDS  16384
#define LW      32
#define NC      64
#define E3      256
#define OUTW    770
#define HD      128          // dims per half
#define HROWB   512u         // bytes per char row in half-table (128 dims * 4B)
#define HBLK    370          // blocks per dim-half
#define NBLKS   (2 * HBLK)   // 740 total
#define WPH     (HBLK * 8)   // 2960 warps per half
#define BLOCKT  256

typedef unsigned long long ull;

static constexpr int TABLE_BYTES = NC * HROWB;                 // 32768
static constexpr int SMEM_BYTES  = TABLE_BYTES + 8 * LW * 4;   // + per-warp offsets

__device__ __forceinline__ void lds128(uint32_t addr, ull &a, ull &b) {
    asm("ld.shared.v2.b64 {%0,%1}, [%2];" : "=l"(a), "=l"(b) : "r"(addr));
}
__device__ __forceinline__ ull add2(ull a, ull b) {
    ull r; asm("add.rn.f32x2 %0, %1, %2;" : "=l"(r) : "l"(a), "l"(b)); return r;
}

__global__ __launch_bounds__(BLOCKT, 5) void opb_kernel(
    const int* __restrict__ sntcs, const float* __restrict__ W,
    float* __restrict__ out)
{
    extern __shared__ float smem[];
    float*    sWT   = smem;                                // [64][128] half-table
    uint32_t* sOffs = (uint32_t*)(smem + NC * HD);         // [8][32] per-warp

    const int tid  = threadIdx.x;
    const int lane = tid & 31;
    const int wj   = tid >> 5;                   // warp in block
    const int h    = (blockIdx.x >= HBLK);       // dim-half owned by this block
    const int hb   = blockIdx.x - h * HBLK;      // block index within half

    // ---- Fill half-table: sWT[c*128 + d'] = W[(h*128+d')*64 + c] ----
    for (int idx = tid; idx < NC * HD; idx += BLOCKT) {
        int d = idx >> 6, c = idx & 63;          // d' in 0..127
        sWT[c * HD + d] = W[(h * HD + d) * NC + c];
    }
    __syncthreads();                             // the only block barrier

    uint32_t sbase;
    asm("{ .reg .u64 t; cvta.to.shared.u64 t, %1; cvt.u32.u64 %0, t; }"
        : "=r"(sbase) : "l"(smem));
    const uint32_t gbase = sbase + (uint32_t)lane * 16u;   // lane's float4 column
    const uint32_t obase = sbase + (uint32_t)(TABLE_BYTES + wj * LW * 4);

    int w = hb * 8 + wj;                         // first word for this warp
    int c_reg = 0;
    if (w < NWORDS) c_reg = sntcs[w * LW + lane];

    while (w < NWORDS) {
        // ---- metadata (warp-local): first-occurrence argmax etc. ----
        int c = c_reg;
        unsigned key = ((unsigned)c << 5) | (unsigned)(31 - lane);
        #pragma unroll
        for (int off = 16; off; off >>= 1) {
            unsigned o = __shfl_xor_sync(0xffffffffu, key, off);
            key = key > o ? key : o;
        }
        int p  = 31 - (int)(key & 31u);          // argmax (first max)
        int wl = p - 1; if (wl < 0) wl = 0;      // relu(argmax - 1)
        int ends = __shfl_sync(0xffffffffu, c, wl);  // gather BEFORE scatter
        int s = (lane == wl) ? 0 : c;            // scatter 0 at wl
        if (lane == 31) s = ends;                // overwrite last with ends
        __syncwarp();                            // prior gather reads done
        sOffs[wj * LW + lane] = (uint32_t)s * HROWB;
        __syncwarp();

        const int wnext = w + WPH;               // prefetch next word's chars
        if (wnext < NWORDS) c_reg = sntcs[wnext * LW + lane];

        // ---- gather: warp covers 128 dims (lane = float4 column) ----
        ull f01 = 0, f23 = 0, l01 = 0, l23 = 0;
        ull a01 = 0, a23 = 0, b01 = 0, b23 = 0;
        const uint4* op = (const uint4*)(sOffs + wj * LW);

        #pragma unroll
        for (int k = 0; k < 8; k++) {
            uint4 ck = op[k];                    // broadcast LDS (uniform addr)
            #pragma unroll
            for (int q = 0; q < 4; q++) {
                const int l = 4 * k + q;
                uint32_t off4 = (q == 0) ? ck.x : (q == 1) ? ck.y
                              : (q == 2) ? ck.z : ck.w;
                ull v01, v23;
                lds128(gbase + off4, v01, v23);
                if (l == 0)            { f01 = v01; f23 = v23; }
                else if (l == LW - 1)  { l01 = v01; l23 = v23; }
                else if (l & 1)        { a01 = add2(a01, v01); a23 = add2(a23, v23); }
                else                   { b01 = add2(b01, v01); b23 = add2(b23, v23); }
            }
        }
        ull s01 = add2(a01, b01), s23 = add2(a23, b23);

        float* o = out + (size_t)w * OUTW + (h * HD + lane * 4);
        *(ull*)(o + 2)        = f01;   // first  (global base+2: 8B aligned)
        *(ull*)(o + 4)        = f23;
        *(ull*)(o + 2 + E3)   = s01;   // bow
        *(ull*)(o + 4 + E3)   = s23;
        *(ull*)(o + 2 + 2*E3) = l01;   // last
        *(ull*)(o + 4 + 2*E3) = l23;
        if (h == 0 && lane == 0)
            *(ull*)(out + (size_t)w * OUTW) = 0ull;   // left zero pad

        w = wnext;
    }
}

extern "C" void kernel_launch(void* const* d_in, const int* in_sizes, int n_in,
                              void* d_out, int out_size)
{
    const int*   sntcs = (const int*)d_in[0];
    const float* W     = (const float*)d_in[1];
    float*       out   = (float*)d_out;

    cudaFuncSetAttribute(opb_kernel, cudaFuncAttributeMaxDynamicSharedMemorySize, SMEM_BYTES);
    opb_kernel<<<NBLKS, BLOCKT, SMEM_BYTES>>>(sntcs, W, out);
}

// round 7
// speedup vs baseline: 1.5868x; 1.5868x over previous
#include <cuda_runtime.h>
#include <cstdint>

#define NWORDS  16384
#define LW      32
#define NC      64
#define E3      256
#define OUTW    770
#define HD      128          // dims per half
#define HPAD    132          // padded floats per char row (4-way-max fill, CF gather)
#define HROWB   528u         // bytes per padded char row
#define HBLK    370          // blocks per dim-half
#define NBLKS   (2 * HBLK)   // 740 total
#define WPH     (HBLK * 8)   // 2960 warps per half
#define BLOCKT  256

typedef unsigned long long ull;

static constexpr int TABLE_FLOATS = NC * HPAD;                     // 8448
static constexpr int SMEM_BYTES   = TABLE_FLOATS * 4 + 8 * LW * 4; // 34816

__device__ __forceinline__ void lds128(uint32_t addr, ull &a, ull &b) {
    asm("ld.shared.v2.b64 {%0,%1}, [%2];" : "=l"(a), "=l"(b) : "r"(addr));
}
__device__ __forceinline__ ull add2(ull a, ull b) {
    ull r; asm("add.rn.f32x2 %0, %1, %2;" : "=l"(r) : "l"(a), "l"(b)); return r;
}

__global__ __launch_bounds__(BLOCKT, 5) void opb_kernel(
    const int* __restrict__ sntcs, const float* __restrict__ W,
    float* __restrict__ out)
{
    extern __shared__ float smem[];
    float*    sWT   = smem;                                // [64][132] half-table
    uint32_t* sOffs = (uint32_t*)(smem + TABLE_FLOATS);    // [8][32] per-warp

    const int tid  = threadIdx.x;
    const int lane = tid & 31;
    const int wj   = tid >> 5;                   // warp in block
    const int h    = (blockIdx.x >= HBLK);       // dim-half owned by this block
    const int hb   = blockIdx.x - h * HBLK;      // block index within half

    // ---- Fill half-table: sWT[c*HPAD + d] = W[(h*128+d)*64 + c] ----
    // LDG coalesced (addr = h*8192 + idx); STS stride 132 -> 4-way max.
    for (int idx = tid; idx < NC * HD; idx += BLOCKT) {
        int d = idx >> 6, c = idx & 63;          // d in 0..127
        sWT[c * HPAD + d] = W[h * (HD * NC) + idx];
    }
    __syncthreads();                             // the only block barrier

    uint32_t sbase;
    asm("{ .reg .u64 t; cvta.to.shared.u64 t, %1; cvt.u32.u64 %0, t; }"
        : "=r"(sbase) : "l"(smem));
    const uint32_t gbase = sbase + (uint32_t)lane * 16u;   // lane's float4 column

    int w = hb * 8 + wj;                         // first word for this warp
    int c_reg = 0;
    if (w < NWORDS) c_reg = sntcs[w * LW + lane];

    while (w < NWORDS) {
        // ---- metadata (warp-local): first-occurrence argmax etc. ----
        int c = c_reg;
        unsigned key = ((unsigned)c << 5) | (unsigned)(31 - lane);
        #pragma unroll
        for (int off = 16; off; off >>= 1) {
            unsigned o = __shfl_xor_sync(0xffffffffu, key, off);
            key = key > o ? key : o;
        }
        int p  = 31 - (int)(key & 31u);          // argmax (first max)
        int wl = p - 1; if (wl < 0) wl = 0;      // relu(argmax - 1)
        int ends = __shfl_sync(0xffffffffu, c, wl);  // gather BEFORE scatter
        int s = (lane == wl) ? 0 : c;            // scatter 0 at wl
        if (lane == 31) s = ends;                // overwrite last with ends
        __syncwarp();
        sOffs[wj * LW + lane] = (uint32_t)s * HROWB;
        __syncwarp();

        const int wnext = w + WPH;               // prefetch next word's chars
        if (wnext < NWORDS) c_reg = sntcs[wnext * LW + lane];

        // ---- gather: warp covers 128 dims (lane = float4 column) ----
        ull f01 = 0, f23 = 0, l01 = 0, l23 = 0;
        ull a01 = 0, a23 = 0, b01 = 0, b23 = 0;
        const uint4* op = (const uint4*)(sOffs + wj * LW);

        #pragma unroll
        for (int k = 0; k < 8; k++) {
            uint4 ck = op[k];                    // broadcast LDS (uniform addr)
            #pragma unroll
            for (int q = 0; q < 4; q++) {
                const int l = 4 * k + q;
                uint32_t off4 = (q == 0) ? ck.x : (q == 1) ? ck.y
                              : (q == 2) ? ck.z : ck.w;
                ull v01, v23;
                lds128(gbase + off4, v01, v23);
                if (l == 0)            { f01 = v01; f23 = v23; }
                else if (l == LW - 1)  { l01 = v01; l23 = v23; }
                else if (l & 1)        { a01 = add2(a01, v01); a23 = add2(a23, v23); }
                else                   { b01 = add2(b01, v01); b23 = add2(b23, v23); }
            }
        }
        ull s01 = add2(a01, b01), s23 = add2(a23, b23);

        float* o = out + (size_t)w * OUTW + (h * HD + lane * 4);
        *(ull*)(o + 2)        = f01;   // first  (global base+2: 8B aligned)
        *(ull*)(o + 4)        = f23;
        *(ull*)(o + 2 + E3)   = s01;   // bow
        *(ull*)(o + 4 + E3)   = s23;
        *(ull*)(o + 2 + 2*E3) = l01;   // last
        *(ull*)(o + 4 + 2*E3) = l23;
        if (h == 0 && lane == 0)
            *(ull*)(out + (size_t)w * OUTW) = 0ull;   // left zero pad

        w = wnext;
    }
}

extern "C" void kernel_launch(void* const* d_in, const int* in_sizes, int n_in,
                              void* d_out, int out_size)
{
    const int*   sntcs = (const int*)d_in[0];
    const float* W     = (const float*)d_in[1];
    float*       out   = (float*)d_out;

    cudaFuncSetAttribute(opb_kernel, cudaFuncAttributeMaxDynamicSharedMemorySize, SMEM_BYTES);
    opb_kernel<<<NBLKS, BLOCKT, SMEM_BYTES>>>(sntcs, W, out);
}